// round 11
// baseline (speedup 1.0000x reference)
#include <cuda_runtime.h>
#include <cuda_bf16.h>
#include <math_constants.h>

#define NNODES 50000
#define NEDGES 800000
#define IN_DIM 128
#define HID    32
#define OUTD   64
#define F1     256   // H1*HID
#define F2     256   // H2*HID

// ---------------- static scratch (no allocations allowed) ----------------
__device__ float    g_bufA[(size_t)NNODES * 256];
__device__ float    g_bufB[(size_t)NNODES * 256];
__device__ int      g_deg[NNODES];
__device__ int      g_pos[NEDGES];
__device__ int      g_rowptr[NNODES + 1];
__device__ int      g_csr[NEDGES];
__device__ unsigned g_gmax[64];

// ---------------- helpers ----------------
__device__ __forceinline__ unsigned enc_f(float f) {
    unsigned u = __float_as_uint(f);
    return (u & 0x80000000u) ? ~u : (u | 0x80000000u);
}

// packed f32x2 FMA: d = a*b + d
__device__ __forceinline__ void ffma2(unsigned long long& d,
                                      unsigned long long a,
                                      unsigned long long b) {
    asm("fma.rn.f32x2 %0, %1, %2, %0;" : "+l"(d) : "l"(a), "l"(b));
}

// build {v,v} packed pair in registers
__device__ __forceinline__ unsigned long long dup2(float v) {
    float2 f = make_float2(v, v);
    return *reinterpret_cast<unsigned long long*>(&f);
}

__device__ __forceinline__ float lrelu(float x) { return fmaxf(x, 0.2f * x); }

// ---------------- CSR build ----------------
__global__ void hist_kernel(const int* __restrict__ dst) {
    int e = blockIdx.x * blockDim.x + threadIdx.x;
    if (e < NEDGES) g_pos[e] = atomicAdd(&g_deg[dst[e]], 1);
}

__global__ void scan_kernel() {
    __shared__ int sums[1024];
    const int t = threadIdx.x;
    const int C = (NNODES + 1023) / 1024;  // 49
    int base = t * C;
    int local = 0;
    for (int i = 0; i < C; i++) {
        int idx = base + i;
        if (idx < NNODES) local += g_deg[idx];
    }
    sums[t] = local;
    __syncthreads();
    for (int off = 1; off < 1024; off <<= 1) {
        int v = (t >= off) ? sums[t - off] : 0;
        __syncthreads();
        sums[t] += v;
        __syncthreads();
    }
    int prefix = (t == 0) ? 0 : sums[t - 1];
    for (int i = 0; i < C; i++) {
        int idx = base + i;
        if (idx < NNODES) { g_rowptr[idx] = prefix; prefix += g_deg[idx]; }
    }
    if (t == 1023) g_rowptr[NNODES] = NEDGES;
}

__global__ void scatter_kernel(const int* __restrict__ src, const int* __restrict__ dst) {
    int e = blockIdx.x * blockDim.x + threadIdx.x;
    if (e < NEDGES) {
        int d = dst[e];
        g_csr[g_rowptr[d] + g_pos[e]] = src[e];
    }
}

// ---------------- GEMM: C[M,Nc] = A[M,K] @ W[K,Nc] + bias -----------------
// Templated on BN_. BM=128, BK=16, (BN_/8 * 16) threads, 8x8 per thread,
// FFMA2 inner loop, register-dup A, double-buffered smem.
// BN_=128 halves A re-reads vs BN=64 for the 256-wide layers.
#define BM 128
#define BK 16
#define BMP2 132          // A row pad

template <int BN_>
__global__ void __launch_bounds__(BN_ * 2) gemm_bias_kernel(
    const float* __restrict__ A, const float* __restrict__ W,
    const float* __restrict__ bias, float* __restrict__ C,
    int M, int K, int Nc)
{
    constexpr int NTHREADS = BN_ * 2;     // (BN_/8)*(BM/8)
    constexpr int TXM = BN_ / 8 - 1;      // tx mask
    constexpr int TXS = (BN_ == 128) ? 4 : 3;
    constexpr int BNP = BN_ + 4;
    constexpr int NB4 = BN_ / 4;          // float4s per B row

    __shared__ float As[2][BK][BMP2];
    __shared__ float Bs[2][BK][BNP];
    const int t  = threadIdx.x;
    const int tx = t & TXM;
    const int ty = t >> TXS;
    const int m0 = blockIdx.y * BM;
    const int n0 = blockIdx.x * BN_;

    // A loader: 512 float4 over NTHREADS threads
    constexpr int AJ = 512 / NTHREADS;
    // B loader: 4*BN_ float4 over NTHREADS threads
    constexpr int BJ = (4 * BN_) / NTHREADS;

    unsigned long long acc2[8][4];
#pragma unroll
    for (int i = 0; i < 8; i++)
#pragma unroll
        for (int j = 0; j < 4; j++) acc2[i][j] = 0ULL;

    float4 va[AJ], vb[BJ];

    auto load_regs = [&](int k0) {
#pragma unroll
        for (int j = 0; j < AJ; j++) {
            int f   = t + NTHREADS * j;
            int row = f >> 2;
            int c4  = f & 3;
            int gr  = m0 + row;
            va[j] = make_float4(0.f, 0.f, 0.f, 0.f);
            if (gr < M)
                va[j] = *(const float4*)(A + (size_t)gr * K + k0 + c4 * 4);
        }
#pragma unroll
        for (int j = 0; j < BJ; j++) {
            int f   = t + NTHREADS * j;
            int row = f / NB4;
            int c4  = f % NB4;
            vb[j] = *(const float4*)(W + (size_t)(k0 + row) * Nc + n0 + c4 * 4);
        }
    };
    auto store_smem = [&](int buf) {
#pragma unroll
        for (int j = 0; j < AJ; j++) {
            int f   = t + NTHREADS * j;
            int row = f >> 2;
            int c4  = f & 3;
            As[buf][c4 * 4 + 0][row] = va[j].x;
            As[buf][c4 * 4 + 1][row] = va[j].y;
            As[buf][c4 * 4 + 2][row] = va[j].z;
            As[buf][c4 * 4 + 3][row] = va[j].w;
        }
#pragma unroll
        for (int j = 0; j < BJ; j++) {
            int f   = t + NTHREADS * j;
            int row = f / NB4;
            int c4  = f % NB4;
            *(float4*)&Bs[buf][row][c4 * 4] = vb[j];
        }
    };

    const int ntiles = K / BK;
    load_regs(0);
    store_smem(0);
    __syncthreads();

    for (int tt = 0; tt < ntiles; tt++) {
        const int buf = tt & 1;
        if (tt + 1 < ntiles) load_regs((tt + 1) * BK);
#pragma unroll
        for (int k = 0; k < BK; k++) {
            float4 alo = *(const float4*)&As[buf][k][ty * 8];
            float4 ahi = *(const float4*)&As[buf][k][ty * 8 + 4];
            unsigned long long a2[8];
            a2[0] = dup2(alo.x); a2[1] = dup2(alo.y);
            a2[2] = dup2(alo.z); a2[3] = dup2(alo.w);
            a2[4] = dup2(ahi.x); a2[5] = dup2(ahi.y);
            a2[6] = dup2(ahi.z); a2[7] = dup2(ahi.w);
            ulonglong2 bv0 = *(const ulonglong2*)&Bs[buf][k][tx * 8];
            ulonglong2 bv1 = *(const ulonglong2*)&Bs[buf][k][tx * 8 + 4];
            unsigned long long b2[4] = {bv0.x, bv0.y, bv1.x, bv1.y};
#pragma unroll
            for (int i = 0; i < 8; i++)
#pragma unroll
                for (int j = 0; j < 4; j++)
                    ffma2(acc2[i][j], a2[i], b2[j]);
        }
        if (tt + 1 < ntiles) store_smem(buf ^ 1);
        __syncthreads();
    }

#pragma unroll
    for (int i = 0; i < 8; i++) {
        int gr = m0 + ty * 8 + i;
        if (gr < M) {
#pragma unroll
            for (int j = 0; j < 2; j++) {
                int gc = n0 + tx * 8 + j * 4;
                float2 p0 = *(float2*)&acc2[i][j * 2 + 0];
                float2 p1 = *(float2*)&acc2[i][j * 2 + 1];
                float4 v;
                v.x = p0.x + bias[gc + 0];
                v.y = p0.y + bias[gc + 1];
                v.z = p1.x + bias[gc + 2];
                v.w = p1.y + bias[gc + 3];
                *(float4*)(C + (size_t)gr * Nc + gc) = v;
            }
        }
    }
}

// --------- online-softmax update for one head slot (float4 payload) --------
__device__ __forceinline__ void upd4(float& m, float& den, float4& acc,
                                     float p, const float4& s)
{
    float nm = fmaxf(m, p);
    float e  = __expf(fminf(m, p) - nm);
    bool  gt = p > m;
    float scale = gt ? e : 1.f;
    float w     = gt ? 1.f : e;
    den   = fmaf(den, scale, w);
    acc.x = fmaf(acc.x, scale, w * s.x);
    acc.y = fmaf(acc.y, scale, w * s.y);
    acc.z = fmaf(acc.z, scale, w * s.z);
    acc.w = fmaf(acc.w, scale, w * s.w);
    m = nm;
}

// leaky-relu(s+d) . a   (4-wide partial)
__device__ __forceinline__ float dp_lr4(const float4& s, const float4& d,
                                        const float4& a)
{
    float p;
    p = lrelu(s.x + d.x) * a.x;
    p = fmaf(lrelu(s.y + d.y), a.y, p);
    p = fmaf(lrelu(s.z + d.z), a.z, p);
    p = fmaf(lrelu(s.w + d.w), a.w, p);
    return p;
}

// ---------------- edge aggregation, H=8 D=32 (layers 1,2) ------------------
__global__ void __launch_bounds__(256) agg_h8_kernel(
    const float* __restrict__ h, const float* __restrict__ attn,
    float* __restrict__ outbuf)
{
    const int warp = (blockIdx.x * blockDim.x + threadIdx.x) >> 5;
    const int lane = threadIdx.x & 31;
    if (warp >= NNODES) return;

    const float4* arow = (const float4*)attn;
    const float4  a0 = arow[lane];
    const float4  a1 = arow[lane + 32];
    const float4* drow = (const float4*)(h + (size_t)warp * 256);
    const float4  d0 = drow[lane];
    const float4  d1 = drow[lane + 32];

    float  m0 = -CUDART_INF_F, m1 = -CUDART_INF_F;
    float  den0 = 0.f, den1 = 0.f;
    float4 acc0 = make_float4(0.f, 0.f, 0.f, 0.f);
    float4 acc1 = make_float4(0.f, 0.f, 0.f, 0.f);

    const int beg = g_rowptr[warp];
    const int end = g_rowptr[warp + 1];
    const int n4  = (end - beg) & ~3;
    int i = beg;

    for (; i < beg + n4; i += 4) {
        int s0i = g_csr[i],     s1i = g_csr[i + 1];
        int s2i = g_csr[i + 2], s3i = g_csr[i + 3];
        const float4* r0 = (const float4*)(h + (size_t)s0i * 256);
        const float4* r1 = (const float4*)(h + (size_t)s1i * 256);
        const float4* r2 = (const float4*)(h + (size_t)s2i * 256);
        const float4* r3 = (const float4*)(h + (size_t)s3i * 256);
        float4 sA0 = r0[lane], sA1 = r0[lane + 32];
        float4 sB0 = r1[lane], sB1 = r1[lane + 32];
        float4 sC0 = r2[lane], sC1 = r2[lane + 32];
        float4 sD0 = r3[lane], sD1 = r3[lane + 32];
        float pA0 = dp_lr4(sA0, d0, a0), pA1 = dp_lr4(sA1, d1, a1);
        float pB0 = dp_lr4(sB0, d0, a0), pB1 = dp_lr4(sB1, d1, a1);
        float pC0 = dp_lr4(sC0, d0, a0), pC1 = dp_lr4(sC1, d1, a1);
        float pD0 = dp_lr4(sD0, d0, a0), pD1 = dp_lr4(sD1, d1, a1);
#pragma unroll
        for (int off = 1; off <= 4; off <<= 1) {
            pA0 += __shfl_xor_sync(0xffffffffu, pA0, off);
            pA1 += __shfl_xor_sync(0xffffffffu, pA1, off);
            pB0 += __shfl_xor_sync(0xffffffffu, pB0, off);
            pB1 += __shfl_xor_sync(0xffffffffu, pB1, off);
            pC0 += __shfl_xor_sync(0xffffffffu, pC0, off);
            pC1 += __shfl_xor_sync(0xffffffffu, pC1, off);
            pD0 += __shfl_xor_sync(0xffffffffu, pD0, off);
            pD1 += __shfl_xor_sync(0xffffffffu, pD1, off);
        }
        upd4(m0, den0, acc0, pA0, sA0); upd4(m1, den1, acc1, pA1, sA1);
        upd4(m0, den0, acc0, pB0, sB0); upd4(m1, den1, acc1, pB1, sB1);
        upd4(m0, den0, acc0, pC0, sC0); upd4(m1, den1, acc1, pC1, sC1);
        upd4(m0, den0, acc0, pD0, sD0); upd4(m1, den1, acc1, pD1, sD1);
    }

    for (; i < end; i++) {
        int s = g_csr[i];
        const float4* srow = (const float4*)(h + (size_t)s * 256);
        float4 s0 = srow[lane], s1 = srow[lane + 32];
        float p0 = dp_lr4(s0, d0, a0);
        float p1 = dp_lr4(s1, d1, a1);
#pragma unroll
        for (int off = 1; off <= 4; off <<= 1) {
            p0 += __shfl_xor_sync(0xffffffffu, p0, off);
            p1 += __shfl_xor_sync(0xffffffffu, p1, off);
        }
        upd4(m0, den0, acc0, p0, s0);
        upd4(m1, den1, acc1, p1, s1);
    }

    const float inv0 = 1.f / den0;
    const float inv1 = 1.f / den1;
    float4 v0, v1;
    v0.x = acc0.x * inv0; v0.y = acc0.y * inv0;
    v0.z = acc0.z * inv0; v0.w = acc0.w * inv0;
    v1.x = acc1.x * inv1; v1.y = acc1.y * inv1;
    v1.z = acc1.z * inv1; v1.w = acc1.w * inv1;
    v0.x = (v0.x > 0.f) ? v0.x : (__expf(v0.x) - 1.f);
    v0.y = (v0.y > 0.f) ? v0.y : (__expf(v0.y) - 1.f);
    v0.z = (v0.z > 0.f) ? v0.z : (__expf(v0.z) - 1.f);
    v0.w = (v0.w > 0.f) ? v0.w : (__expf(v0.w) - 1.f);
    v1.x = (v1.x > 0.f) ? v1.x : (__expf(v1.x) - 1.f);
    v1.y = (v1.y > 0.f) ? v1.y : (__expf(v1.y) - 1.f);
    v1.z = (v1.z > 0.f) ? v1.z : (__expf(v1.z) - 1.f);
    v1.w = (v1.w > 0.f) ? v1.w : (__expf(v1.w) - 1.f);

    float4* orow = (float4*)(outbuf + (size_t)warp * 256);
    orow[lane]      = v0;
    orow[lane + 32] = v1;
}

// ---------------- layer 3: H=1 D=64, packed float2, fused max-pool ---------
__global__ void __launch_bounds__(256) agg_out_kernel(
    const float* __restrict__ h, const float* __restrict__ attn)
{
    __shared__ unsigned sred[64];
    const int tid = threadIdx.x;
    if (tid < 64) sred[tid] = 0u;
    __syncthreads();

    const int warp = (blockIdx.x * blockDim.x + tid) >> 5;
    const int lane = tid & 31;
    if (warp < NNODES) {
        const float2 a = ((const float2*)attn)[lane];
        const float2 d = ((const float2*)(h + (size_t)warp * 64))[lane];
        float m = -CUDART_INF_F, den = 0.f;
        float2 acc = make_float2(0.f, 0.f);
        const int beg = g_rowptr[warp];
        const int end = g_rowptr[warp + 1];
        for (int i = beg; i < end; i++) {
            int s = g_csr[i];
            const float2 sv = ((const float2*)(h + (size_t)s * 64))[lane];
            float p = lrelu(sv.x + d.x) * a.x;
            p = fmaf(lrelu(sv.y + d.y), a.y, p);
#pragma unroll
            for (int off = 16; off > 0; off >>= 1)
                p += __shfl_xor_sync(0xffffffffu, p, off);
            float nm = fmaxf(m, p);
            float e  = __expf(fminf(m, p) - nm);
            bool  gt = p > m;
            float scale = gt ? e : 1.f;
            float w     = gt ? 1.f : e;
            den   = fmaf(den, scale, w);
            acc.x = fmaf(acc.x, scale, w * sv.x);
            acc.y = fmaf(acc.y, scale, w * sv.y);
            m = nm;
        }
        float inv = 1.f / den;
        atomicMax(&sred[2 * lane],     enc_f(acc.x * inv));
        atomicMax(&sred[2 * lane + 1], enc_f(acc.y * inv));
    }
    __syncthreads();
    if (tid < 64) atomicMax(&g_gmax[tid], sred[tid]);
}

__global__ void final_kernel(float* __restrict__ out) {
    int i = threadIdx.x;
    unsigned k = g_gmax[i];
    unsigned u = (k & 0x80000000u) ? (k ^ 0x80000000u) : ~k;
    out[i] = __uint_as_float(u);
}

// ---------------- launch ----------------
extern "C" void kernel_launch(void* const* d_in, const int* in_sizes, int n_in,
                              void* d_out, int out_size)
{
    const float* x     = (const float*)d_in[0];
    const int*   src   = (const int*)  d_in[1];
    const int*   dst   = (const int*)  d_in[2];
    const float* W1    = (const float*)d_in[3];
    const float* b1    = (const float*)d_in[4];
    const float* attn1 = (const float*)d_in[5];
    const float* W2    = (const float*)d_in[6];
    const float* b2    = (const float*)d_in[7];
    const float* attn2 = (const float*)d_in[8];
    const float* W3    = (const float*)d_in[9];
    const float* b3    = (const float*)d_in[10];
    const float* attn3 = (const float*)d_in[11];
    float* out = (float*)d_out;

    float *bufA = nullptr, *bufB = nullptr;
    void  *degp = nullptr, *gmaxp = nullptr;
    cudaGetSymbolAddress((void**)&bufA, g_bufA);
    cudaGetSymbolAddress((void**)&bufB, g_bufB);
    cudaGetSymbolAddress(&degp,  g_deg);
    cudaGetSymbolAddress(&gmaxp, g_gmax);

    // one-time side-stream + fork/join events
    static cudaStream_t s1 = nullptr;
    static cudaEvent_t  evF = nullptr, evJ = nullptr;
    if (!s1) {
        cudaStreamCreateWithFlags(&s1, cudaStreamNonBlocking);
        cudaEventCreateWithFlags(&evF, cudaEventDisableTiming);
        cudaEventCreateWithFlags(&evJ, cudaEventDisableTiming);
    }

    const int mtiles = (NNODES + BM - 1) / BM;   // 391
    const int aggblk = (NNODES + 7) / 8;         // 6250

    // fork: CSR build on s1, GEMM1 on main stream (independent)
    cudaEventRecord(evF, 0);
    cudaStreamWaitEvent(s1, evF, 0);

    cudaMemsetAsync(degp,  0, NNODES * sizeof(int), s1);
    cudaMemsetAsync(gmaxp, 0, 64 * sizeof(unsigned), s1);
    hist_kernel<<<(NEDGES + 255) / 256, 256, 0, s1>>>(dst);
    scan_kernel<<<1, 1024, 0, s1>>>();
    scatter_kernel<<<(NEDGES + 255) / 256, 256, 0, s1>>>(src, dst);
    cudaEventRecord(evJ, s1);

    // layer 1 GEMM (BN=128) runs concurrently with CSR build
    gemm_bias_kernel<128><<<dim3(F1 / 128, mtiles), 256>>>(x, W1, b1, bufA, NNODES, IN_DIM, F1);

    // join: agg needs the CSR
    cudaStreamWaitEvent(0, evJ, 0);
    agg_h8_kernel<<<aggblk, 256>>>(bufA, attn1, bufB);
    // layer 2
    gemm_bias_kernel<128><<<dim3(F2 / 128, mtiles), 256>>>(bufB, W2, b2, bufA, NNODES, F1, F2);
    agg_h8_kernel<<<aggblk, 256>>>(bufA, attn2, bufB);
    // layer 3 (Nc=64 -> BN=64 instantiation)
    gemm_bias_kernel<64><<<dim3(1, mtiles), 128>>>(bufB, W3, b3, bufA, NNODES, F2, OUTD);
    agg_out_kernel<<<aggblk, 256>>>(bufA, attn3);

    final_kernel<<<1, 64>>>(out);
}

// round 13
// speedup vs baseline: 1.0499x; 1.0499x over previous
#include <cuda_runtime.h>
#include <cuda_bf16.h>
#include <math_constants.h>
#include <cstdint>

#define NNODES 50000
#define NEDGES 800000
#define IN_DIM 128
#define HID    32
#define OUTD   64
#define F1     256   // H1*HID
#define F2     256   // H2*HID

// ---------------- static scratch (no allocations allowed) ----------------
__device__ float    g_bufA[(size_t)NNODES * 256];
__device__ float    g_bufB[(size_t)NNODES * 256];
__device__ int      g_deg[NNODES];
__device__ int      g_pos[NEDGES];
__device__ int      g_rowptr[NNODES + 1];
__device__ int      g_csr[NEDGES];
__device__ unsigned g_gmax[64];

// ---------------- helpers ----------------
__device__ __forceinline__ unsigned enc_f(float f) {
    unsigned u = __float_as_uint(f);
    return (u & 0x80000000u) ? ~u : (u | 0x80000000u);
}

// packed f32x2 FMA: d = a*b + d
__device__ __forceinline__ void ffma2(unsigned long long& d,
                                      unsigned long long a,
                                      unsigned long long b) {
    asm("fma.rn.f32x2 %0, %1, %2, %0;" : "+l"(d) : "l"(a), "l"(b));
}

// build {v,v} packed pair in registers
__device__ __forceinline__ unsigned long long dup2(float v) {
    float2 f = make_float2(v, v);
    return *reinterpret_cast<unsigned long long*>(&f);
}

__device__ __forceinline__ void cp_async16(unsigned int saddr, const void* gptr) {
    asm volatile("cp.async.ca.shared.global [%0], [%1], 16;"
                 :: "r"(saddr), "l"(gptr));
}
__device__ __forceinline__ void cp_commit() {
    asm volatile("cp.async.commit_group;");
}
__device__ __forceinline__ void cp_wait0() {
    asm volatile("cp.async.wait_group 0;" ::: "memory");
}

__device__ __forceinline__ float lrelu(float x) { return fmaxf(x, 0.2f * x); }

// ---------------- CSR build ----------------
__global__ void hist_kernel(const int* __restrict__ dst) {
    int e = blockIdx.x * blockDim.x + threadIdx.x;
    if (e < NEDGES) g_pos[e] = atomicAdd(&g_deg[dst[e]], 1);
}

__global__ void scan_kernel() {
    __shared__ int sums[1024];
    const int t = threadIdx.x;
    const int C = (NNODES + 1023) / 1024;  // 49
    int base = t * C;
    int local = 0;
    for (int i = 0; i < C; i++) {
        int idx = base + i;
        if (idx < NNODES) local += g_deg[idx];
    }
    sums[t] = local;
    __syncthreads();
    for (int off = 1; off < 1024; off <<= 1) {
        int v = (t >= off) ? sums[t - off] : 0;
        __syncthreads();
        sums[t] += v;
        __syncthreads();
    }
    int prefix = (t == 0) ? 0 : sums[t - 1];
    for (int i = 0; i < C; i++) {
        int idx = base + i;
        if (idx < NNODES) { g_rowptr[idx] = prefix; prefix += g_deg[idx]; }
    }
    if (t == 1023) g_rowptr[NNODES] = NEDGES;
}

__global__ void scatter_kernel(const int* __restrict__ src, const int* __restrict__ dst) {
    int e = blockIdx.x * blockDim.x + threadIdx.x;
    if (e < NEDGES) {
        int d = dst[e];
        g_csr[g_rowptr[d] + g_pos[e]] = src[e];
    }
}

// ---------------- GEMM: C[M,Nc] = A[M,K] @ W[K,Nc] + bias -----------------
// BM=128, BN=64, BK=8, 128 threads, 8x8 per thread, FFMA2 inner loop.
// A via register staging (transpose), B via cp.async (no staging regs).
// __launch_bounds__(128,4): 4 CTAs/SM for latency hiding.
#define BM 128
#define BN 64
#define BK 8
#define BMP2 132          // A row pad
#define BNP  68           // B row pad (272B rows, 16B-aligned)

__global__ void __launch_bounds__(128, 4) gemm_bias_kernel(
    const float* __restrict__ A, const float* __restrict__ W,
    const float* __restrict__ bias, float* __restrict__ C,
    int M, int K, int Nc)
{
    __shared__ float As[2][BK][BMP2];
    __shared__ float Bs[2][BK][BNP];
    const int t  = threadIdx.x;
    const int tx = t & 7;
    const int ty = t >> 3;
    const int m0 = blockIdx.y * BM;
    const int n0 = blockIdx.x * BN;

    // A loader: 128 rows x 2 float4 = 256 float4, 2 per thread
    const int arow = t >> 1;           // 0..63, +64 for j=1
    const int ac4  = t & 1;            // which 16B chunk of the 8-k row
    // B loader: 8 rows x 16 float4 = 128 chunks, 1 per thread
    const int brow = t >> 4;
    const int bc4  = t & 15;

    unsigned long long acc2[8][4];
#pragma unroll
    for (int i = 0; i < 8; i++)
#pragma unroll
        for (int j = 0; j < 4; j++) acc2[i][j] = 0ULL;

    float4 va[2];

    auto load_regsA = [&](int k0) {
#pragma unroll
        for (int j = 0; j < 2; j++) {
            int row = arow + 64 * j;
            int gr  = m0 + row;
            va[j] = make_float4(0.f, 0.f, 0.f, 0.f);
            if (gr < M)
                va[j] = *(const float4*)(A + (size_t)gr * K + k0 + ac4 * 4);
        }
    };
    auto store_smemA = [&](int buf) {
#pragma unroll
        for (int j = 0; j < 2; j++) {
            int row = arow + 64 * j;
            As[buf][ac4 * 4 + 0][row] = va[j].x;
            As[buf][ac4 * 4 + 1][row] = va[j].y;
            As[buf][ac4 * 4 + 2][row] = va[j].z;
            As[buf][ac4 * 4 + 3][row] = va[j].w;
        }
    };
    auto issue_cpB = [&](int k0, int buf) {
        unsigned int saddr = (unsigned int)__cvta_generic_to_shared(&Bs[buf][brow][bc4 * 4]);
        cp_async16(saddr, W + (size_t)(k0 + brow) * Nc + n0 + bc4 * 4);
        cp_commit();
    };

    const int ntiles = K / BK;
    load_regsA(0);
    issue_cpB(0, 0);
    store_smemA(0);
    cp_wait0();
    __syncthreads();

    for (int tt = 0; tt < ntiles; tt++) {
        const int buf = tt & 1;
        if (tt + 1 < ntiles) {
            issue_cpB((tt + 1) * BK, buf ^ 1);
            load_regsA((tt + 1) * BK);
        }
#pragma unroll
        for (int k = 0; k < BK; k++) {
            float4 alo = *(const float4*)&As[buf][k][ty * 8];
            float4 ahi = *(const float4*)&As[buf][k][ty * 8 + 4];
            unsigned long long a2[8];
            a2[0] = dup2(alo.x); a2[1] = dup2(alo.y);
            a2[2] = dup2(alo.z); a2[3] = dup2(alo.w);
            a2[4] = dup2(ahi.x); a2[5] = dup2(ahi.y);
            a2[6] = dup2(ahi.z); a2[7] = dup2(ahi.w);
            ulonglong2 bv0 = *(const ulonglong2*)&Bs[buf][k][tx * 8];
            ulonglong2 bv1 = *(const ulonglong2*)&Bs[buf][k][tx * 8 + 4];
            unsigned long long b2[4] = {bv0.x, bv0.y, bv1.x, bv1.y};
#pragma unroll
            for (int i = 0; i < 8; i++)
#pragma unroll
                for (int j = 0; j < 4; j++)
                    ffma2(acc2[i][j], a2[i], b2[j]);
        }
        if (tt + 1 < ntiles) {
            store_smemA(buf ^ 1);
            cp_wait0();
        }
        __syncthreads();
    }

#pragma unroll
    for (int i = 0; i < 8; i++) {
        int gr = m0 + ty * 8 + i;
        if (gr < M) {
#pragma unroll
            for (int j = 0; j < 2; j++) {
                int gc = n0 + tx * 8 + j * 4;
                float2 p0 = *(float2*)&acc2[i][j * 2 + 0];
                float2 p1 = *(float2*)&acc2[i][j * 2 + 1];
                float4 v;
                v.x = p0.x + bias[gc + 0];
                v.y = p0.y + bias[gc + 1];
                v.z = p1.x + bias[gc + 2];
                v.w = p1.y + bias[gc + 3];
                *(float4*)(C + (size_t)gr * Nc + gc) = v;
            }
        }
    }
}

// --------- online-softmax update for one head slot (float4 payload) --------
__device__ __forceinline__ void upd4(float& m, float& den, float4& acc,
                                     float p, const float4& s)
{
    float nm = fmaxf(m, p);
    float e  = __expf(fminf(m, p) - nm);
    bool  gt = p > m;
    float scale = gt ? e : 1.f;
    float w     = gt ? 1.f : e;
    den   = fmaf(den, scale, w);
    acc.x = fmaf(acc.x, scale, w * s.x);
    acc.y = fmaf(acc.y, scale, w * s.y);
    acc.z = fmaf(acc.z, scale, w * s.z);
    acc.w = fmaf(acc.w, scale, w * s.w);
    m = nm;
}

// leaky-relu(s+d) . a   (4-wide partial)
__device__ __forceinline__ float dp_lr4(const float4& s, const float4& d,
                                        const float4& a)
{
    float p;
    p = lrelu(s.x + d.x) * a.x;
    p = fmaf(lrelu(s.y + d.y), a.y, p);
    p = fmaf(lrelu(s.z + d.z), a.z, p);
    p = fmaf(lrelu(s.w + d.w), a.w, p);
    return p;
}

// ---------------- edge aggregation, H=8 D=32 (layers 1,2) ------------------
__global__ void __launch_bounds__(256) agg_h8_kernel(
    const float* __restrict__ h, const float* __restrict__ attn,
    float* __restrict__ outbuf)
{
    const int warp = (blockIdx.x * blockDim.x + threadIdx.x) >> 5;
    const int lane = threadIdx.x & 31;
    if (warp >= NNODES) return;

    const float4* arow = (const float4*)attn;
    const float4  a0 = arow[lane];
    const float4  a1 = arow[lane + 32];
    const float4* drow = (const float4*)(h + (size_t)warp * 256);
    const float4  d0 = drow[lane];
    const float4  d1 = drow[lane + 32];

    float  m0 = -CUDART_INF_F, m1 = -CUDART_INF_F;
    float  den0 = 0.f, den1 = 0.f;
    float4 acc0 = make_float4(0.f, 0.f, 0.f, 0.f);
    float4 acc1 = make_float4(0.f, 0.f, 0.f, 0.f);

    const int beg = g_rowptr[warp];
    const int end = g_rowptr[warp + 1];
    const int n4  = (end - beg) & ~3;
    int i = beg;

    for (; i < beg + n4; i += 4) {
        int s0i = g_csr[i],     s1i = g_csr[i + 1];
        int s2i = g_csr[i + 2], s3i = g_csr[i + 3];
        const float4* r0 = (const float4*)(h + (size_t)s0i * 256);
        const float4* r1 = (const float4*)(h + (size_t)s1i * 256);
        const float4* r2 = (const float4*)(h + (size_t)s2i * 256);
        const float4* r3 = (const float4*)(h + (size_t)s3i * 256);
        float4 sA0 = r0[lane], sA1 = r0[lane + 32];
        float4 sB0 = r1[lane], sB1 = r1[lane + 32];
        float4 sC0 = r2[lane], sC1 = r2[lane + 32];
        float4 sD0 = r3[lane], sD1 = r3[lane + 32];
        float pA0 = dp_lr4(sA0, d0, a0), pA1 = dp_lr4(sA1, d1, a1);
        float pB0 = dp_lr4(sB0, d0, a0), pB1 = dp_lr4(sB1, d1, a1);
        float pC0 = dp_lr4(sC0, d0, a0), pC1 = dp_lr4(sC1, d1, a1);
        float pD0 = dp_lr4(sD0, d0, a0), pD1 = dp_lr4(sD1, d1, a1);
#pragma unroll
        for (int off = 1; off <= 4; off <<= 1) {
            pA0 += __shfl_xor_sync(0xffffffffu, pA0, off);
            pA1 += __shfl_xor_sync(0xffffffffu, pA1, off);
            pB0 += __shfl_xor_sync(0xffffffffu, pB0, off);
            pB1 += __shfl_xor_sync(0xffffffffu, pB1, off);
            pC0 += __shfl_xor_sync(0xffffffffu, pC0, off);
            pC1 += __shfl_xor_sync(0xffffffffu, pC1, off);
            pD0 += __shfl_xor_sync(0xffffffffu, pD0, off);
            pD1 += __shfl_xor_sync(0xffffffffu, pD1, off);
        }
        upd4(m0, den0, acc0, pA0, sA0); upd4(m1, den1, acc1, pA1, sA1);
        upd4(m0, den0, acc0, pB0, sB0); upd4(m1, den1, acc1, pB1, sB1);
        upd4(m0, den0, acc0, pC0, sC0); upd4(m1, den1, acc1, pC1, sC1);
        upd4(m0, den0, acc0, pD0, sD0); upd4(m1, den1, acc1, pD1, sD1);
    }

    for (; i < end; i++) {
        int s = g_csr[i];
        const float4* srow = (const float4*)(h + (size_t)s * 256);
        float4 s0 = srow[lane], s1 = srow[lane + 32];
        float p0 = dp_lr4(s0, d0, a0);
        float p1 = dp_lr4(s1, d1, a1);
#pragma unroll
        for (int off = 1; off <= 4; off <<= 1) {
            p0 += __shfl_xor_sync(0xffffffffu, p0, off);
            p1 += __shfl_xor_sync(0xffffffffu, p1, off);
        }
        upd4(m0, den0, acc0, p0, s0);
        upd4(m1, den1, acc1, p1, s1);
    }

    const float inv0 = 1.f / den0;
    const float inv1 = 1.f / den1;
    float4 v0, v1;
    v0.x = acc0.x * inv0; v0.y = acc0.y * inv0;
    v0.z = acc0.z * inv0; v0.w = acc0.w * inv0;
    v1.x = acc1.x * inv1; v1.y = acc1.y * inv1;
    v1.z = acc1.z * inv1; v1.w = acc1.w * inv1;
    v0.x = (v0.x > 0.f) ? v0.x : (__expf(v0.x) - 1.f);
    v0.y = (v0.y > 0.f) ? v0.y : (__expf(v0.y) - 1.f);
    v0.z = (v0.z > 0.f) ? v0.z : (__expf(v0.z) - 1.f);
    v0.w = (v0.w > 0.f) ? v0.w : (__expf(v0.w) - 1.f);
    v1.x = (v1.x > 0.f) ? v1.x : (__expf(v1.x) - 1.f);
    v1.y = (v1.y > 0.f) ? v1.y : (__expf(v1.y) - 1.f);
    v1.z = (v1.z > 0.f) ? v1.z : (__expf(v1.z) - 1.f);
    v1.w = (v1.w > 0.f) ? v1.w : (__expf(v1.w) - 1.f);

    float4* orow = (float4*)(outbuf + (size_t)warp * 256);
    orow[lane]      = v0;
    orow[lane + 32] = v1;
}

// ---------------- layer 3: H=1 D=64, packed float2, fused max-pool ---------
__global__ void __launch_bounds__(256) agg_out_kernel(
    const float* __restrict__ h, const float* __restrict__ attn)
{
    __shared__ unsigned sred[64];
    const int tid = threadIdx.x;
    if (tid < 64) sred[tid] = 0u;
    __syncthreads();

    const int warp = (blockIdx.x * blockDim.x + tid) >> 5;
    const int lane = tid & 31;
    if (warp < NNODES) {
        const float2 a = ((const float2*)attn)[lane];
        const float2 d = ((const float2*)(h + (size_t)warp * 64))[lane];
        float m = -CUDART_INF_F, den = 0.f;
        float2 acc = make_float2(0.f, 0.f);
        const int beg = g_rowptr[warp];
        const int end = g_rowptr[warp + 1];
        for (int i = beg; i < end; i++) {
            int s = g_csr[i];
            const float2 sv = ((const float2*)(h + (size_t)s * 64))[lane];
            float p = lrelu(sv.x + d.x) * a.x;
            p = fmaf(lrelu(sv.y + d.y), a.y, p);
#pragma unroll
            for (int off = 16; off > 0; off >>= 1)
                p += __shfl_xor_sync(0xffffffffu, p, off);
            float nm = fmaxf(m, p);
            float e  = __expf(fminf(m, p) - nm);
            bool  gt = p > m;
            float scale = gt ? e : 1.f;
            float w     = gt ? 1.f : e;
            den   = fmaf(den, scale, w);
            acc.x = fmaf(acc.x, scale, w * sv.x);
            acc.y = fmaf(acc.y, scale, w * sv.y);
            m = nm;
        }
        float inv = 1.f / den;
        atomicMax(&sred[2 * lane],     enc_f(acc.x * inv));
        atomicMax(&sred[2 * lane + 1], enc_f(acc.y * inv));
    }
    __syncthreads();
    if (tid < 64) atomicMax(&g_gmax[tid], sred[tid]);
}

__global__ void final_kernel(float* __restrict__ out) {
    int i = threadIdx.x;
    unsigned k = g_gmax[i];
    unsigned u = (k & 0x80000000u) ? (k ^ 0x80000000u) : ~k;
    out[i] = __uint_as_float(u);
}

// ---------------- launch ----------------
extern "C" void kernel_launch(void* const* d_in, const int* in_sizes, int n_in,
                              void* d_out, int out_size)
{
    const float* x     = (const float*)d_in[0];
    const int*   src   = (const int*)  d_in[1];
    const int*   dst   = (const int*)  d_in[2];
    const float* W1    = (const float*)d_in[3];
    const float* b1    = (const float*)d_in[4];
    const float* attn1 = (const float*)d_in[5];
    const float* W2    = (const float*)d_in[6];
    const float* b2    = (const float*)d_in[7];
    const float* attn2 = (const float*)d_in[8];
    const float* W3    = (const float*)d_in[9];
    const float* b3    = (const float*)d_in[10];
    const float* attn3 = (const float*)d_in[11];
    float* out = (float*)d_out;

    float *bufA = nullptr, *bufB = nullptr;
    void  *degp = nullptr, *gmaxp = nullptr;
    cudaGetSymbolAddress((void**)&bufA, g_bufA);
    cudaGetSymbolAddress((void**)&bufB, g_bufB);
    cudaGetSymbolAddress(&degp,  g_deg);
    cudaGetSymbolAddress(&gmaxp, g_gmax);

    // one-time side-stream + fork/join events
    static cudaStream_t s1 = nullptr;
    static cudaEvent_t  evF = nullptr, evJ = nullptr;
    if (!s1) {
        cudaStreamCreateWithFlags(&s1, cudaStreamNonBlocking);
        cudaEventCreateWithFlags(&evF, cudaEventDisableTiming);
        cudaEventCreateWithFlags(&evJ, cudaEventDisableTiming);
    }

    const int mtiles = (NNODES + BM - 1) / BM;   // 391
    const int aggblk = (NNODES + 7) / 8;         // 6250

    // fork: CSR build on s1, GEMM1 on main stream (independent)
    cudaEventRecord(evF, 0);
    cudaStreamWaitEvent(s1, evF, 0);

    cudaMemsetAsync(degp,  0, NNODES * sizeof(int), s1);
    cudaMemsetAsync(gmaxp, 0, 64 * sizeof(unsigned), s1);
    hist_kernel<<<(NEDGES + 255) / 256, 256, 0, s1>>>(dst);
    scan_kernel<<<1, 1024, 0, s1>>>();
    scatter_kernel<<<(NEDGES + 255) / 256, 256, 0, s1>>>(src, dst);
    cudaEventRecord(evJ, s1);

    // layer 1 GEMM runs concurrently with CSR build
    gemm_bias_kernel<<<dim3(F1 / BN, mtiles), 128>>>(x, W1, b1, bufA, NNODES, IN_DIM, F1);

    // join: agg needs the CSR
    cudaStreamWaitEvent(0, evJ, 0);
    agg_h8_kernel<<<aggblk, 256>>>(bufA, attn1, bufB);
    // layer 2
    gemm_bias_kernel<<<dim3(F2 / BN, mtiles), 128>>>(bufB, W2, b2, bufA, NNODES, F1, F2);
    agg_h8_kernel<<<aggblk, 256>>>(bufA, attn2, bufB);
    // layer 3
    gemm_bias_kernel<<<dim3(OUTD / BN, mtiles), 128>>>(bufB, W3, b3, bufA, NNODES, F2, OUTD);
    agg_out_kernel<<<aggblk, 256>>>(bufA, attn3);

    final_kernel<<<1, 64>>>(out);
}

// round 15
// speedup vs baseline: 1.1296x; 1.0758x over previous
#include <cuda_runtime.h>
#include <cuda_bf16.h>
#include <math_constants.h>
#include <cstdint>

#define NNODES 50000
#define NEDGES 800000
#define IN_DIM 128
#define HID    32
#define OUTD   64
#define F1     256   // H1*HID
#define F2     256   // H2*HID

// ---------------- static scratch (no allocations allowed) ----------------
__device__ float    g_bufA[(size_t)NNODES * 256];
__device__ float    g_bufB[(size_t)NNODES * 256];
__device__ int      g_deg[NNODES];
__device__ int      g_pos[NEDGES];
__device__ int      g_rowptr[NNODES + 1];
__device__ int      g_csr[NEDGES];
__device__ unsigned g_gmax[64];

// ---------------- helpers ----------------
__device__ __forceinline__ unsigned enc_f(float f) {
    unsigned u = __float_as_uint(f);
    return (u & 0x80000000u) ? ~u : (u | 0x80000000u);
}

// packed f32x2 FMA: d = a*b + d
__device__ __forceinline__ void ffma2(unsigned long long& d,
                                      unsigned long long a,
                                      unsigned long long b) {
    asm("fma.rn.f32x2 %0, %1, %2, %0;" : "+l"(d) : "l"(a), "l"(b));
}

// build {v,v} packed pair in registers
__device__ __forceinline__ unsigned long long dup2(float v) {
    float2 f = make_float2(v, v);
    return *reinterpret_cast<unsigned long long*>(&f);
}

__device__ __forceinline__ void cp_async16(unsigned int saddr, const void* gptr) {
    asm volatile("cp.async.ca.shared.global [%0], [%1], 16;"
                 :: "r"(saddr), "l"(gptr));
}
__device__ __forceinline__ void cp_commit() {
    asm volatile("cp.async.commit_group;");
}
__device__ __forceinline__ void cp_wait0() {
    asm volatile("cp.async.wait_group 0;" ::: "memory");
}

__device__ __forceinline__ float lrelu(float x) { return fmaxf(x, 0.2f * x); }

// profiling-window shim: shifts ncu's -s 5 so agg_h8 is captured
__global__ void noop_kernel() {}

// ---------------- CSR build ----------------
__global__ void hist_kernel(const int* __restrict__ dst) {
    int e = blockIdx.x * blockDim.x + threadIdx.x;
    if (e < NEDGES) g_pos[e] = atomicAdd(&g_deg[dst[e]], 1);
}

__global__ void scan_kernel() {
    __shared__ int sums[1024];
    const int t = threadIdx.x;
    const int C = (NNODES + 1023) / 1024;  // 49
    int base = t * C;
    int local = 0;
    for (int i = 0; i < C; i++) {
        int idx = base + i;
        if (idx < NNODES) local += g_deg[idx];
    }
    sums[t] = local;
    __syncthreads();
    for (int off = 1; off < 1024; off <<= 1) {
        int v = (t >= off) ? sums[t - off] : 0;
        __syncthreads();
        sums[t] += v;
        __syncthreads();
    }
    int prefix = (t == 0) ? 0 : sums[t - 1];
    for (int i = 0; i < C; i++) {
        int idx = base + i;
        if (idx < NNODES) { g_rowptr[idx] = prefix; prefix += g_deg[idx]; }
    }
    if (t == 1023) g_rowptr[NNODES] = NEDGES;
}

__global__ void scatter_kernel(const int* __restrict__ src, const int* __restrict__ dst) {
    int e = blockIdx.x * blockDim.x + threadIdx.x;
    if (e < NEDGES) {
        int d = dst[e];
        g_csr[g_rowptr[d] + g_pos[e]] = src[e];
    }
}

// ---------------- GEMM: C[M,Nc] = A[M,K] @ W[K,Nc] + bias -----------------
// R10 shape: BM=128, BN=64, BK=16, 128 threads, 8x8/thread, FFMA2,
// register-staged A (transpose), cp.async B (contiguous rows), 1 sync/tile.
#define BM 128
#define BN 64
#define BK 16
#define BMP2 132          // A row pad
#define BNP  68           // B row pad

__global__ void __launch_bounds__(128) gemm_bias_kernel(
    const float* __restrict__ A, const float* __restrict__ W,
    const float* __restrict__ bias, float* __restrict__ C,
    int M, int K, int Nc)
{
    __shared__ float As[2][BK][BMP2];
    __shared__ float Bs[2][BK][BNP];
    const int t  = threadIdx.x;
    const int tx = t & 7;
    const int ty = t >> 3;
    const int m0 = blockIdx.y * BM;
    const int n0 = blockIdx.x * BN;

    const int arow0 = t >> 2;          // + 32*j
    const int ac4   = t & 3;
    const int brow0 = t >> 4;          // + 8*j
    const int bc4   = t & 15;

    unsigned long long acc2[8][4];
#pragma unroll
    for (int i = 0; i < 8; i++)
#pragma unroll
        for (int j = 0; j < 4; j++) acc2[i][j] = 0ULL;

    float4 va[4];

    auto load_regsA = [&](int k0) {
#pragma unroll
        for (int j = 0; j < 4; j++) {
            int row = arow0 + 32 * j;
            int gr  = m0 + row;
            va[j] = make_float4(0.f, 0.f, 0.f, 0.f);
            if (gr < M)
                va[j] = *(const float4*)(A + (size_t)gr * K + k0 + ac4 * 4);
        }
    };
    auto store_smemA = [&](int buf) {
#pragma unroll
        for (int j = 0; j < 4; j++) {
            int row = arow0 + 32 * j;
            As[buf][ac4 * 4 + 0][row] = va[j].x;
            As[buf][ac4 * 4 + 1][row] = va[j].y;
            As[buf][ac4 * 4 + 2][row] = va[j].z;
            As[buf][ac4 * 4 + 3][row] = va[j].w;
        }
    };
    auto issue_cpB = [&](int k0, int buf) {
#pragma unroll
        for (int j = 0; j < 2; j++) {
            int row = brow0 + 8 * j;
            unsigned int saddr =
                (unsigned int)__cvta_generic_to_shared(&Bs[buf][row][bc4 * 4]);
            cp_async16(saddr, W + (size_t)(k0 + row) * Nc + n0 + bc4 * 4);
        }
        cp_commit();
    };

    const int ntiles = K / BK;
    load_regsA(0);
    issue_cpB(0, 0);
    store_smemA(0);
    cp_wait0();
    __syncthreads();

    for (int tt = 0; tt < ntiles; tt++) {
        const int buf = tt & 1;
        if (tt + 1 < ntiles) {
            issue_cpB((tt + 1) * BK, buf ^ 1);
            load_regsA((tt + 1) * BK);
        }
#pragma unroll
        for (int k = 0; k < BK; k++) {
            float4 alo = *(const float4*)&As[buf][k][ty * 8];
            float4 ahi = *(const float4*)&As[buf][k][ty * 8 + 4];
            unsigned long long a2[8];
            a2[0] = dup2(alo.x); a2[1] = dup2(alo.y);
            a2[2] = dup2(alo.z); a2[3] = dup2(alo.w);
            a2[4] = dup2(ahi.x); a2[5] = dup2(ahi.y);
            a2[6] = dup2(ahi.z); a2[7] = dup2(ahi.w);
            ulonglong2 bv0 = *(const ulonglong2*)&Bs[buf][k][tx * 8];
            ulonglong2 bv1 = *(const ulonglong2*)&Bs[buf][k][tx * 8 + 4];
            unsigned long long b2[4] = {bv0.x, bv0.y, bv1.x, bv1.y};
#pragma unroll
            for (int i = 0; i < 8; i++)
#pragma unroll
                for (int j = 0; j < 4; j++)
                    ffma2(acc2[i][j], a2[i], b2[j]);
        }
        if (tt + 1 < ntiles) {
            store_smemA(buf ^ 1);
            cp_wait0();
        }
        __syncthreads();
    }

#pragma unroll
    for (int i = 0; i < 8; i++) {
        int gr = m0 + ty * 8 + i;
        if (gr < M) {
#pragma unroll
            for (int j = 0; j < 2; j++) {
                int gc = n0 + tx * 8 + j * 4;
                float2 p0 = *(float2*)&acc2[i][j * 2 + 0];
                float2 p1 = *(float2*)&acc2[i][j * 2 + 1];
                float4 v;
                v.x = p0.x + bias[gc + 0];
                v.y = p0.y + bias[gc + 1];
                v.z = p1.x + bias[gc + 2];
                v.w = p1.y + bias[gc + 3];
                *(float4*)(C + (size_t)gr * Nc + gc) = v;
            }
        }
    }
}

// --------- online-softmax update for one head slot (float4 payload) --------
__device__ __forceinline__ void upd4(float& m, float& den, float4& acc,
                                     float p, const float4& s)
{
    float nm = fmaxf(m, p);
    float e  = __expf(fminf(m, p) - nm);
    bool  gt = p > m;
    float scale = gt ? e : 1.f;
    float w     = gt ? 1.f : e;
    den   = fmaf(den, scale, w);
    acc.x = fmaf(acc.x, scale, w * s.x);
    acc.y = fmaf(acc.y, scale, w * s.y);
    acc.z = fmaf(acc.z, scale, w * s.z);
    acc.w = fmaf(acc.w, scale, w * s.w);
    m = nm;
}

// leaky-relu(s+d) . a   (4-wide partial)
__device__ __forceinline__ float dp_lr4(const float4& s, const float4& d,
                                        const float4& a)
{
    float p;
    p = lrelu(s.x + d.x) * a.x;
    p = fmaf(lrelu(s.y + d.y), a.y, p);
    p = fmaf(lrelu(s.z + d.z), a.z, p);
    p = fmaf(lrelu(s.w + d.w), a.w, p);
    return p;
}

// ---------------- edge aggregation, H=8 D=32 (layers 1,2) ------------------
__global__ void __launch_bounds__(256) agg_h8_kernel(
    const float* __restrict__ h, const float* __restrict__ attn,
    float* __restrict__ outbuf)
{
    const int warp = (blockIdx.x * blockDim.x + threadIdx.x) >> 5;
    const int lane = threadIdx.x & 31;
    if (warp >= NNODES) return;

    const float4* arow = (const float4*)attn;
    const float4  a0 = arow[lane];
    const float4  a1 = arow[lane + 32];
    const float4* drow = (const float4*)(h + (size_t)warp * 256);
    const float4  d0 = drow[lane];
    const float4  d1 = drow[lane + 32];

    float  m0 = -CUDART_INF_F, m1 = -CUDART_INF_F;
    float  den0 = 0.f, den1 = 0.f;
    float4 acc0 = make_float4(0.f, 0.f, 0.f, 0.f);
    float4 acc1 = make_float4(0.f, 0.f, 0.f, 0.f);

    const int beg = g_rowptr[warp];
    const int end = g_rowptr[warp + 1];
    const int n4  = (end - beg) & ~3;
    int i = beg;

    for (; i < beg + n4; i += 4) {
        int s0i = g_csr[i],     s1i = g_csr[i + 1];
        int s2i = g_csr[i + 2], s3i = g_csr[i + 3];
        const float4* r0 = (const float4*)(h + (size_t)s0i * 256);
        const float4* r1 = (const float4*)(h + (size_t)s1i * 256);
        const float4* r2 = (const float4*)(h + (size_t)s2i * 256);
        const float4* r3 = (const float4*)(h + (size_t)s3i * 256);
        float4 sA0 = r0[lane], sA1 = r0[lane + 32];
        float4 sB0 = r1[lane], sB1 = r1[lane + 32];
        float4 sC0 = r2[lane], sC1 = r2[lane + 32];
        float4 sD0 = r3[lane], sD1 = r3[lane + 32];
        float pA0 = dp_lr4(sA0, d0, a0), pA1 = dp_lr4(sA1, d1, a1);
        float pB0 = dp_lr4(sB0, d0, a0), pB1 = dp_lr4(sB1, d1, a1);
        float pC0 = dp_lr4(sC0, d0, a0), pC1 = dp_lr4(sC1, d1, a1);
        float pD0 = dp_lr4(sD0, d0, a0), pD1 = dp_lr4(sD1, d1, a1);
#pragma unroll
        for (int off = 1; off <= 4; off <<= 1) {
            pA0 += __shfl_xor_sync(0xffffffffu, pA0, off);
            pA1 += __shfl_xor_sync(0xffffffffu, pA1, off);
            pB0 += __shfl_xor_sync(0xffffffffu, pB0, off);
            pB1 += __shfl_xor_sync(0xffffffffu, pB1, off);
            pC0 += __shfl_xor_sync(0xffffffffu, pC0, off);
            pC1 += __shfl_xor_sync(0xffffffffu, pC1, off);
            pD0 += __shfl_xor_sync(0xffffffffu, pD0, off);
            pD1 += __shfl_xor_sync(0xffffffffu, pD1, off);
        }
        upd4(m0, den0, acc0, pA0, sA0); upd4(m1, den1, acc1, pA1, sA1);
        upd4(m0, den0, acc0, pB0, sB0); upd4(m1, den1, acc1, pB1, sB1);
        upd4(m0, den0, acc0, pC0, sC0); upd4(m1, den1, acc1, pC1, sC1);
        upd4(m0, den0, acc0, pD0, sD0); upd4(m1, den1, acc1, pD1, sD1);
    }

    for (; i < end; i++) {
        int s = g_csr[i];
        const float4* srow = (const float4*)(h + (size_t)s * 256);
        float4 s0 = srow[lane], s1 = srow[lane + 32];
        float p0 = dp_lr4(s0, d0, a0);
        float p1 = dp_lr4(s1, d1, a1);
#pragma unroll
        for (int off = 1; off <= 4; off <<= 1) {
            p0 += __shfl_xor_sync(0xffffffffu, p0, off);
            p1 += __shfl_xor_sync(0xffffffffu, p1, off);
        }
        upd4(m0, den0, acc0, p0, s0);
        upd4(m1, den1, acc1, p1, s1);
    }

    const float inv0 = 1.f / den0;
    const float inv1 = 1.f / den1;
    float4 v0, v1;
    v0.x = acc0.x * inv0; v0.y = acc0.y * inv0;
    v0.z = acc0.z * inv0; v0.w = acc0.w * inv0;
    v1.x = acc1.x * inv1; v1.y = acc1.y * inv1;
    v1.z = acc1.z * inv1; v1.w = acc1.w * inv1;
    v0.x = (v0.x > 0.f) ? v0.x : (__expf(v0.x) - 1.f);
    v0.y = (v0.y > 0.f) ? v0.y : (__expf(v0.y) - 1.f);
    v0.z = (v0.z > 0.f) ? v0.z : (__expf(v0.z) - 1.f);
    v0.w = (v0.w > 0.f) ? v0.w : (__expf(v0.w) - 1.f);
    v1.x = (v1.x > 0.f) ? v1.x : (__expf(v1.x) - 1.f);
    v1.y = (v1.y > 0.f) ? v1.y : (__expf(v1.y) - 1.f);
    v1.z = (v1.z > 0.f) ? v1.z : (__expf(v1.z) - 1.f);
    v1.w = (v1.w > 0.f) ? v1.w : (__expf(v1.w) - 1.f);

    float4* orow = (float4*)(outbuf + (size_t)warp * 256);
    orow[lane]      = v0;
    orow[lane + 32] = v1;
}

// ---------------- layer 3: H=1 D=64, packed float2, fused max-pool ---------
__global__ void __launch_bounds__(256) agg_out_kernel(
    const float* __restrict__ h, const float* __restrict__ attn)
{
    __shared__ unsigned sred[64];
    const int tid = threadIdx.x;
    if (tid < 64) sred[tid] = 0u;
    __syncthreads();

    const int warp = (blockIdx.x * blockDim.x + tid) >> 5;
    const int lane = tid & 31;
    if (warp < NNODES) {
        const float2 a = ((const float2*)attn)[lane];
        const float2 d = ((const float2*)(h + (size_t)warp * 64))[lane];
        float m = -CUDART_INF_F, den = 0.f;
        float2 acc = make_float2(0.f, 0.f);
        const int beg = g_rowptr[warp];
        const int end = g_rowptr[warp + 1];
        for (int i = beg; i < end; i++) {
            int s = g_csr[i];
            const float2 sv = ((const float2*)(h + (size_t)s * 64))[lane];
            float p = lrelu(sv.x + d.x) * a.x;
            p = fmaf(lrelu(sv.y + d.y), a.y, p);
#pragma unroll
            for (int off = 16; off > 0; off >>= 1)
                p += __shfl_xor_sync(0xffffffffu, p, off);
            float nm = fmaxf(m, p);
            float e  = __expf(fminf(m, p) - nm);
            bool  gt = p > m;
            float scale = gt ? e : 1.f;
            float w     = gt ? 1.f : e;
            den   = fmaf(den, scale, w);
            acc.x = fmaf(acc.x, scale, w * sv.x);
            acc.y = fmaf(acc.y, scale, w * sv.y);
            m = nm;
        }
        float inv = 1.f / den;
        atomicMax(&sred[2 * lane],     enc_f(acc.x * inv));
        atomicMax(&sred[2 * lane + 1], enc_f(acc.y * inv));
    }
    __syncthreads();
    if (tid < 64) atomicMax(&g_gmax[tid], sred[tid]);
}

__global__ void final_kernel(float* __restrict__ out) {
    int i = threadIdx.x;
    unsigned k = g_gmax[i];
    unsigned u = (k & 0x80000000u) ? (k ^ 0x80000000u) : ~k;
    out[i] = __uint_as_float(u);
}

// ---------------- launch ----------------
extern "C" void kernel_launch(void* const* d_in, const int* in_sizes, int n_in,
                              void* d_out, int out_size)
{
    const float* x     = (const float*)d_in[0];
    const int*   src   = (const int*)  d_in[1];
    const int*   dst   = (const int*)  d_in[2];
    const float* W1    = (const float*)d_in[3];
    const float* b1    = (const float*)d_in[4];
    const float* attn1 = (const float*)d_in[5];
    const float* W2    = (const float*)d_in[6];
    const float* b2    = (const float*)d_in[7];
    const float* attn2 = (const float*)d_in[8];
    const float* W3    = (const float*)d_in[9];
    const float* b3    = (const float*)d_in[10];
    const float* attn3 = (const float*)d_in[11];
    float* out = (float*)d_out;

    float *bufA = nullptr, *bufB = nullptr;
    void  *degp = nullptr, *gmaxp = nullptr;
    cudaGetSymbolAddress((void**)&bufA, g_bufA);
    cudaGetSymbolAddress((void**)&bufB, g_bufB);
    cudaGetSymbolAddress(&degp,  g_deg);
    cudaGetSymbolAddress(&gmaxp, g_gmax);

    // one-time side-stream + fork/join events
    static cudaStream_t s1 = nullptr;
    static cudaEvent_t  evF = nullptr, evJ = nullptr;
    if (!s1) {
        cudaStreamCreateWithFlags(&s1, cudaStreamNonBlocking);
        cudaEventCreateWithFlags(&evF, cudaEventDisableTiming);
        cudaEventCreateWithFlags(&evJ, cudaEventDisableTiming);
    }

    const int mtiles = (NNODES + BM - 1) / BM;   // 391
    const int aggblk = (NNODES + 7) / 8;         // 6250

    // noop shifts the ncu -s 5 window onto agg_h8 (launch #6)
    noop_kernel<<<1, 32>>>();

    // fork: CSR build on s1, GEMM1 on main stream (independent)
    cudaEventRecord(evF, 0);
    cudaStreamWaitEvent(s1, evF, 0);

    cudaMemsetAsync(degp,  0, NNODES * sizeof(int), s1);
    cudaMemsetAsync(gmaxp, 0, 64 * sizeof(unsigned), s1);
    hist_kernel<<<(NEDGES + 255) / 256, 256, 0, s1>>>(dst);
    scan_kernel<<<1, 1024, 0, s1>>>();
    scatter_kernel<<<(NEDGES + 255) / 256, 256, 0, s1>>>(src, dst);
    cudaEventRecord(evJ, s1);

    // layer 1 GEMM runs concurrently with CSR build
    gemm_bias_kernel<<<dim3(F1 / BN, mtiles), 128>>>(x, W1, b1, bufA, NNODES, IN_DIM, F1);

    // join: agg needs the CSR
    cudaStreamWaitEvent(0, evJ, 0);
    agg_h8_kernel<<<aggblk, 256>>>(bufA, attn1, bufB);
    // layer 2
    gemm_bias_kernel<<<dim3(F2 / BN, mtiles), 128>>>(bufB, W2, b2, bufA, NNODES, F1, F2);
    agg_h8_kernel<<<aggblk, 256>>>(bufA, attn2, bufB);
    // layer 3
    gemm_bias_kernel<<<dim3(OUTD / BN, mtiles), 128>>>(bufB, W3, b3, bufA, NNODES, F2, OUTD);
    agg_out_kernel<<<aggblk, 256>>>(bufA, attn3);

    final_kernel<<<1, 64>>>(out);
}